// round 8
// baseline (speedup 1.0000x reference)
#include <cuda_runtime.h>
#include <cuda_bf16.h>
#include <cstdint>

#define DIM     64
#define KC      8192
#define NP      32768
#define KS      192          // split-K: [hi|lo|hi] x [hi|hi|lo]
#define MT      128          // points per CTA
#define NT      64           // codes per tile
#define NTILES  (KC / NT)    // 128
#define GT      256

__device__ __align__(16) __nv_bfloat16 d_A[NP * KS];   // 12.6 MB
__device__ __align__(16) __nv_bfloat16 d_B[KC * KS];   // 3.1 MB
__device__ float d_cn[KC];
__device__ int2  d_cand[NP];
__device__ int   d_idx[NP];

// SMEM layout (gemm): A 128x400B | B 2x 64x400B | cn 2x 256B
#define S_A    0
#define S_B    51200
#define S_CN   102400
#define SMEM_G 102912

// ---------------------------------------------------------------------------
// helpers (all generic PTX, sm_80+)
// ---------------------------------------------------------------------------
__device__ __forceinline__ uint32_t smem_u32(const void* p) {
    uint32_t a;
    asm("{ .reg .u64 t; cvta.to.shared.u64 t, %1; cvt.u32.u64 %0, t; }"
        : "=r"(a) : "l"(p));
    return a;
}
__device__ __forceinline__ void cpa16(uint32_t dst, const void* src) {
    asm volatile("cp.async.cg.shared.global [%0], [%1], 16;" :: "r"(dst), "l"(src)
                 : "memory");
}
__device__ __forceinline__ void cpa4(uint32_t dst, const void* src) {
    asm volatile("cp.async.ca.shared.global [%0], [%1], 4;" :: "r"(dst), "l"(src)
                 : "memory");
}
#define CP_COMMIT() asm volatile("cp.async.commit_group;" ::: "memory")
#define CP_WAIT1()  asm volatile("cp.async.wait_group 1;" ::: "memory")

__device__ __forceinline__ void ldm_x4(uint32_t* r, uint32_t addr) {
    asm volatile("ldmatrix.sync.aligned.m8n8.x4.shared.b16 {%0,%1,%2,%3}, [%4];"
                 : "=r"(r[0]), "=r"(r[1]), "=r"(r[2]), "=r"(r[3]) : "r"(addr));
}
__device__ __forceinline__ void mma_bf16(float* d, const uint32_t* a,
                                         uint32_t b0, uint32_t b1) {
    asm volatile(
        "mma.sync.aligned.m16n8k16.row.col.f32.bf16.bf16.f32 "
        "{%0,%1,%2,%3}, {%4,%5,%6,%7}, {%8,%9}, {%0,%1,%2,%3};"
        : "+f"(d[0]), "+f"(d[1]), "+f"(d[2]), "+f"(d[3])
        : "r"(a[0]), "r"(a[1]), "r"(a[2]), "r"(a[3]), "r"(b0), "r"(b1));
}

// ---------------------------------------------------------------------------
// prep kernels
// ---------------------------------------------------------------------------
__global__ void __launch_bounds__(256) prep_cn(const float* __restrict__ cb) {
    int k = blockIdx.x * 256 + threadIdx.x;
    const float* row = cb + (size_t)k * DIM;
    float s = 0.f;
#pragma unroll
    for (int i = 0; i < DIM; i++)
        s = __fadd_rn(s, __fmul_rn(row[i], row[i]));
    d_cn[k] = s;
}

// A' rows: [hi(d0..63) | lo | hi]
__global__ void __launch_bounds__(128) prep_A(const float* __restrict__ ze) {
    __shared__ float xs[DIM * 64];
    const int tid = threadIdx.x;
    const int n0  = blockIdx.x * 64;
    const int b   = n0 >> 12;
    const int hw0 = n0 & 4095;
    const float* zb = ze + (size_t)b * DIM * 4096 + hw0;
#pragma unroll
    for (int it = 0; it < 32; it++) {
        int e = tid + it * 128;
        int nl = e & 63, d = e >> 6;
        xs[d * 64 + nl] = zb[(size_t)d * 4096 + nl];
    }
    __syncthreads();
    uint32_t* out = (uint32_t*)d_A;
#pragma unroll
    for (int i = 0; i < 48; i++) {
        int e   = tid + i * 128;      // 0..6143
        int nl  = e / 96;
        int c   = e % 96;             // uint col (2 bf16)
        int blk = c >> 5;             // 0:hi 1:lo 2:hi
        int d0  = (c & 31) * 2;
        float v0 = xs[d0 * 64 + nl], v1 = xs[(d0 + 1) * 64 + nl];
        __nv_bfloat16 h0 = __float2bfloat16(v0);
        __nv_bfloat16 h1 = __float2bfloat16(v1);
        if (blk == 1) {
            h0 = __float2bfloat16(v0 - __bfloat162float(h0));
            h1 = __float2bfloat16(v1 - __bfloat162float(h1));
        }
        out[(size_t)(n0 + nl) * 96 + c] =
            (uint32_t)__bfloat16_as_ushort(h0) |
            ((uint32_t)__bfloat16_as_ushort(h1) << 16);
    }
}

// B' rows: [hi | hi | lo]
__global__ void __launch_bounds__(256) prep_B(const float* __restrict__ cb) {
    int idx = blockIdx.x * 256 + threadIdx.x;   // 0 .. 8192*96-1
    int row = idx / 96;
    int c   = idx % 96;
    int blk = c >> 5;                 // 0:hi 1:hi 2:lo
    int d0  = (c & 31) * 2;
    float v0 = cb[(size_t)row * 64 + d0], v1 = cb[(size_t)row * 64 + d0 + 1];
    __nv_bfloat16 h0 = __float2bfloat16(v0);
    __nv_bfloat16 h1 = __float2bfloat16(v1);
    if (blk == 2) {
        h0 = __float2bfloat16(v0 - __bfloat162float(h0));
        h1 = __float2bfloat16(v1 - __bfloat162float(h1));
    }
    ((uint32_t*)d_B)[(size_t)row * 96 + c] =
        (uint32_t)__bfloat16_as_ushort(h0) | ((uint32_t)__bfloat16_as_ushort(h1) << 16);
}

// ---------------------------------------------------------------------------
// GEMM (mma.sync bf16) + fused lazy top-2 epilogue
// ---------------------------------------------------------------------------
__device__ __forceinline__ void load_B_tile(uint32_t sb, int t, int buf, int tid) {
#pragma unroll
    for (int i = 0; i < 6; i++) {
        int e = tid + GT * i;         // 0..1535
        int row = e / 24, c = e % 24;
        cpa16(sb + S_B + buf * 25600 + row * 400 + c * 16,
              d_B + (size_t)(t * NT + row) * KS + c * 8);
    }
    if (tid < NT)
        cpa4(sb + S_CN + buf * 256 + tid * 4, d_cn + t * NT + tid);
}

__global__ void __launch_bounds__(GT, 2) gemm_kernel() {
    extern __shared__ char smem[];
    const uint32_t sb = smem_u32(smem);
    const int tid = threadIdx.x;
    const int wid = tid >> 5;
    const int l   = tid & 31;
    const int wm  = wid & 3;          // M-warp 0..3 (32 rows each)
    const int wn  = wid >> 2;         // N-warp 0..1 (32 cols each)
    const int m0  = blockIdx.x * MT;

    // A tile (once, grouped with B0)
#pragma unroll
    for (int i = 0; i < 12; i++) {
        int e = tid + GT * i;         // 0..3071
        int row = e / 24, c = e % 24;
        cpa16(sb + S_A + row * 400 + c * 16, d_A + (size_t)(m0 + row) * KS + c * 8);
    }
    load_B_tile(sb, 0, 0, tid);
    CP_COMMIT();
    load_B_tile(sb, 1, 1, tid);
    CP_COMMIT();
    CP_WAIT1();
    __syncthreads();                  // A + B0 ready

    // ldmatrix per-thread base addresses
    const uint32_t aA0 = sb + S_A + (wm * 32 + (l & 15)) * 400 + (l >> 4) * 16;
    const uint32_t aA1 = aA0 + 16 * 400;
    const uint32_t bRow = (uint32_t)(wn * 32 + (l & 7) + ((l >> 3) & 1) * 8);
    const uint32_t aB0 = sb + S_B + bRow * 400 + (l >> 4) * 16;
    const uint32_t aB1 = aB0 + 16 * 400;

    // column base for this thread's epilogue slice
    const int cb0 = wn * 32 + 2 * (l & 3);

    float b1[4], b2[4];
    int   i1[4], i2[4];
#pragma unroll
    for (int s = 0; s < 4; s++) { b1[s] = 3.4e38f; b2[s] = 3.4e38f; i1[s] = 0; i2[s] = 0; }

#pragma unroll 1
    for (int t = 0; t < NTILES; t++) {
        const int buf = t & 1;
        const uint32_t boff = (uint32_t)buf * 25600;

        float acc[2][4][4];
#pragma unroll
        for (int mt = 0; mt < 2; mt++)
#pragma unroll
            for (int j = 0; j < 4; j++)
#pragma unroll
                for (int q = 0; q < 4; q++) acc[mt][j][q] = 0.f;

#pragma unroll
        for (int ks = 0; ks < 12; ks++) {
            const uint32_t koff = (uint32_t)(ks * 32);   // 16 bf16 = 32 B
            uint32_t ra0[4], ra1[4], rb01[4], rb23[4];
            ldm_x4(ra0,  aA0 + koff);
            ldm_x4(ra1,  aA1 + koff);
            ldm_x4(rb01, aB0 + boff + koff);
            ldm_x4(rb23, aB1 + boff + koff);
            mma_bf16(acc[0][0], ra0, rb01[0], rb01[2]);
            mma_bf16(acc[0][1], ra0, rb01[1], rb01[3]);
            mma_bf16(acc[0][2], ra0, rb23[0], rb23[2]);
            mma_bf16(acc[0][3], ra0, rb23[1], rb23[3]);
            mma_bf16(acc[1][0], ra1, rb01[0], rb01[2]);
            mma_bf16(acc[1][1], ra1, rb01[1], rb01[3]);
            mma_bf16(acc[1][2], ra1, rb23[0], rb23[2]);
            mma_bf16(acc[1][3], ra1, rb23[1], rb23[3]);
        }

        // hoist cn slice into regs (cn[buf] gets overwritten by t+2 loads)
        const float* cnp = (const float*)(smem + S_CN + buf * 256);
        float creg[8];
#pragma unroll
        for (int j = 0; j < 4; j++) {
            creg[2 * j]     = cnp[cb0 + j * 8];
            creg[2 * j + 1] = cnp[cb0 + j * 8 + 1];
        }

        __syncthreads();                       // all warps done reading buf
        if (t + 2 < NTILES) load_B_tile(sb, t + 2, buf, tid);
        CP_COMMIT();                           // cp.async overlaps epilogue below

        // lazy top-2 epilogue: score = nc - 2*m, per row-slot
        const int kb0 = t * NT + cb0;
#pragma unroll
        for (int mt = 0; mt < 2; mt++) {
#pragma unroll
            for (int half = 0; half < 2; half++) {
                const int s = mt * 2 + half;
                float v[8];
#pragma unroll
                for (int j = 0; j < 4; j++) {
                    v[2 * j]     = fmaf(-2.f, acc[mt][j][2 * half],     creg[2 * j]);
                    v[2 * j + 1] = fmaf(-2.f, acc[mt][j][2 * half + 1], creg[2 * j + 1]);
                }
                float m01 = fminf(v[0], v[1]);
                float m23 = fminf(v[2], v[3]);
                float m45 = fminf(v[4], v[5]);
                float m67 = fminf(v[6], v[7]);
                float vmin = fminf(fminf(m01, m23), fminf(m45, m67));
                if (vmin < b2[s]) {            // rare after warm-up
#pragma unroll
                    for (int e = 0; e < 8; e++) {
                        int kk = kb0 + (e >> 1) * 8 + (e & 1);
                        if (v[e] < b1[s]) {
                            b2[s] = b1[s]; i2[s] = i1[s];
                            b1[s] = v[e];  i1[s] = kk;
                        } else if (v[e] < b2[s]) {
                            b2[s] = v[e];  i2[s] = kk;
                        }
                    }
                }
            }
        }

        CP_WAIT1();                            // B(t+1) ready
        __syncthreads();
    }

    // quad merge (lanes sharing l>>2 hold same rows)
#pragma unroll
    for (int s = 0; s < 4; s++) {
#pragma unroll
        for (int off = 1; off <= 2; off <<= 1) {
            float t1 = __shfl_xor_sync(0xFFFFFFFFu, b1[s], off);
            int   j1 = __shfl_xor_sync(0xFFFFFFFFu, i1[s], off);
            float t2 = __shfl_xor_sync(0xFFFFFFFFu, b2[s], off);
            int   j2 = __shfl_xor_sync(0xFFFFFFFFu, i2[s], off);
            if (t1 < b1[s]) {
                float nb2 = fminf(b1[s], t2);
                int   ni2 = (t2 < b1[s]) ? j2 : i1[s];
                b1[s] = t1; i1[s] = j1; b2[s] = nb2; i2[s] = ni2;
            } else if (t1 < b2[s]) {
                b2[s] = t1; i2[s] = j1;
            }
        }
    }

    // cross-N-warp merge via smem (reuse B region)
    float4* red = (float4*)(smem + S_B);       // [128 rows][2 wn]
    if ((l & 3) == 0) {
#pragma unroll
        for (int s = 0; s < 4; s++) {
            int row = wm * 32 + (s >> 1) * 16 + (s & 1) * 8 + (l >> 2);
            red[row * 2 + wn] = make_float4(b1[s], __int_as_float(i1[s]),
                                            b2[s], __int_as_float(i2[s]));
        }
    }
    __syncthreads();
    if (tid < MT) {
        float4 A4 = red[tid * 2 + 0];
        float4 B4 = red[tid * 2 + 1];
        float s1 = A4.x, s2 = A4.z;
        int   k1 = __float_as_int(A4.y), k2 = __float_as_int(A4.w);
        float t1 = B4.x, t2 = B4.z;
        int   j1 = __float_as_int(B4.y), j2 = __float_as_int(B4.w);
        if (t1 < s1) {
            float n2 = fminf(s1, t2);
            int   n2i = (t2 < s1) ? j2 : k1;
            s1 = t1; k1 = j1; s2 = n2; k2 = n2i;
        } else if (t1 < s2) {
            s2 = t1; k2 = j1;
        }
        d_cand[m0 + tid] = make_int2(k1, k2);
    }
}

// ---------------------------------------------------------------------------
// Exact rescore of the 2 candidates with reference-identical rounding
// ---------------------------------------------------------------------------
__global__ void __launch_bounds__(256) rescore(const float* __restrict__ ze,
                                               const float* __restrict__ cb) {
    int n = blockIdx.x * 256 + threadIdx.x;
    int b = n >> 12, hw = n & 4095;
    float x[DIM];
#pragma unroll
    for (int d = 0; d < DIM; d++)
        x[d] = ze[(size_t)(b * DIM + d) * 4096 + hw];
    float nx = 0.f;
#pragma unroll
    for (int d = 0; d < DIM; d++)
        nx = __fadd_rn(nx, __fmul_rn(x[d], x[d]));
    int2 cd = d_cand[n];
    int ka = min(cd.x, cd.y), kb = max(cd.x, cd.y);
    const float* ra = cb + (size_t)ka * DIM;
    const float* rb = cb + (size_t)kb * DIM;
    float ma = 0.f, mb = 0.f;
#pragma unroll
    for (int d = 0; d < DIM; d++) {
        ma = __fmaf_rn(x[d], ra[d], ma);
        mb = __fmaf_rn(x[d], rb[d], mb);
    }
    float d2a = __fadd_rn(__fadd_rn(nx, -__fmul_rn(2.0f, ma)), d_cn[ka]);
    float d2b = __fadd_rn(__fadd_rn(nx, -__fmul_rn(2.0f, mb)), d_cn[kb]);
    d_idx[n] = (d2b < d2a) ? kb : ka;   // strict: tie -> lower index
}

// ---------------------------------------------------------------------------
// Gather z_q
// ---------------------------------------------------------------------------
__global__ void __launch_bounds__(128) gather(const float* __restrict__ cb,
                                              float* __restrict__ out) {
    __shared__ int bx[64];
    const int tid = threadIdx.x;
    const int n0  = blockIdx.x * 64;
    const int b   = n0 >> 12;
    const int hw0 = n0 & 4095;
    if (tid < 64) bx[tid] = d_idx[n0 + tid];
    __syncthreads();
    float* ob = out + (size_t)b * DIM * 4096 + hw0;
#pragma unroll
    for (int it = 0; it < 32; it++) {
        int e = tid + it * 128;
        int nl = e & 63, d = e >> 6;
        ob[(size_t)d * 4096 + nl] = cb[(size_t)bx[nl] * DIM + d];
    }
}

extern "C" void kernel_launch(void* const* d_in, const int* in_sizes, int n_in,
                              void* d_out, int out_size) {
    const float* ze = (const float*)d_in[0];   // [8,64,64,64] f32
    const float* cb = (const float*)d_in[1];   // [8192,64] f32
    float* out = (float*)d_out;

    cudaFuncSetAttribute(gemm_kernel, cudaFuncAttributeMaxDynamicSharedMemorySize,
                         SMEM_G);

    prep_cn<<<KC / 256, 256>>>(cb);
    prep_A<<<NP / 64, 128>>>(ze);
    prep_B<<<(KC * 96) / 256, 256>>>(cb);
    gemm_kernel<<<NP / MT, GT, SMEM_G>>>();
    rescore<<<NP / 256, 256>>>(ze, cb);
    gather<<<NP / 64, 128>>>(cb, out);
}

// round 9
// speedup vs baseline: 1.6157x; 1.6157x over previous
#include <cuda_runtime.h>
#include <cuda_bf16.h>
#include <cstdint>

#define DIM     64
#define KC      8192
#define NP      32768
#define KS      192          // split-K: [hi|lo|hi] x [hi|hi|lo]
#define MT      128          // points per CTA
#define NT      64           // codes per tile
#define NTILES  (KC / NT)    // 128
#define GT      256

__device__ __align__(16) __nv_bfloat16 d_A[NP * KS];   // 12.6 MB
__device__ __align__(16) __nv_bfloat16 d_B[KC * KS];   // 3.1 MB
__device__ float d_cn[KC];
__device__ int2  d_cand[NP];

// SMEM layout (gemm): A 128x400B | B 2x 64x400B | cn 2x 256B
#define S_A    0
#define S_B    51200
#define S_CN   102400
#define SMEM_G 102912

// ---------------------------------------------------------------------------
// helpers (all generic PTX, sm_80+)
// ---------------------------------------------------------------------------
__device__ __forceinline__ uint32_t smem_u32(const void* p) {
    uint32_t a;
    asm("{ .reg .u64 t; cvta.to.shared.u64 t, %1; cvt.u32.u64 %0, t; }"
        : "=r"(a) : "l"(p));
    return a;
}
__device__ __forceinline__ void cpa16(uint32_t dst, const void* src) {
    asm volatile("cp.async.cg.shared.global [%0], [%1], 16;" :: "r"(dst), "l"(src)
                 : "memory");
}
__device__ __forceinline__ void cpa4(uint32_t dst, const void* src) {
    asm volatile("cp.async.ca.shared.global [%0], [%1], 4;" :: "r"(dst), "l"(src)
                 : "memory");
}
#define CP_COMMIT() asm volatile("cp.async.commit_group;" ::: "memory")
#define CP_WAIT1()  asm volatile("cp.async.wait_group 1;" ::: "memory")

__device__ __forceinline__ void ldm_x4(uint32_t* r, uint32_t addr) {
    asm volatile("ldmatrix.sync.aligned.m8n8.x4.shared.b16 {%0,%1,%2,%3}, [%4];"
                 : "=r"(r[0]), "=r"(r[1]), "=r"(r[2]), "=r"(r[3]) : "r"(addr));
}
__device__ __forceinline__ void mma_bf16(float* d, const uint32_t* a,
                                         uint32_t b0, uint32_t b1) {
    asm volatile(
        "mma.sync.aligned.m16n8k16.row.col.f32.bf16.bf16.f32 "
        "{%0,%1,%2,%3}, {%4,%5,%6,%7}, {%8,%9}, {%0,%1,%2,%3};"
        : "+f"(d[0]), "+f"(d[1]), "+f"(d[2]), "+f"(d[3])
        : "r"(a[0]), "r"(a[1]), "r"(a[2]), "r"(a[3]), "r"(b0), "r"(b1));
}

// ---------------------------------------------------------------------------
// prep kernels
// ---------------------------------------------------------------------------
__global__ void __launch_bounds__(256) prep_cn(const float* __restrict__ cb) {
    int k = blockIdx.x * 256 + threadIdx.x;
    const float* row = cb + (size_t)k * DIM;
    float s = 0.f;
#pragma unroll
    for (int i = 0; i < DIM; i++)
        s = __fadd_rn(s, __fmul_rn(row[i], row[i]));
    d_cn[k] = s;
}

// A' rows: [hi(d0..63) | lo | hi]
__global__ void __launch_bounds__(128) prep_A(const float* __restrict__ ze) {
    __shared__ float xs[DIM * 64];
    const int tid = threadIdx.x;
    const int n0  = blockIdx.x * 64;
    const int b   = n0 >> 12;
    const int hw0 = n0 & 4095;
    const float* zb = ze + (size_t)b * DIM * 4096 + hw0;
#pragma unroll
    for (int it = 0; it < 32; it++) {
        int e = tid + it * 128;
        int nl = e & 63, d = e >> 6;
        xs[d * 64 + nl] = zb[(size_t)d * 4096 + nl];
    }
    __syncthreads();
    uint32_t* out = (uint32_t*)d_A;
#pragma unroll
    for (int i = 0; i < 48; i++) {
        int e   = tid + i * 128;      // 0..6143
        int nl  = e / 96;
        int c   = e % 96;             // uint col (2 bf16)
        int blk = c >> 5;             // 0:hi 1:lo 2:hi
        int d0  = (c & 31) * 2;
        float v0 = xs[d0 * 64 + nl], v1 = xs[(d0 + 1) * 64 + nl];
        __nv_bfloat16 h0 = __float2bfloat16(v0);
        __nv_bfloat16 h1 = __float2bfloat16(v1);
        if (blk == 1) {
            h0 = __float2bfloat16(v0 - __bfloat162float(h0));
            h1 = __float2bfloat16(v1 - __bfloat162float(h1));
        }
        out[(size_t)(n0 + nl) * 96 + c] =
            (uint32_t)__bfloat16_as_ushort(h0) |
            ((uint32_t)__bfloat16_as_ushort(h1) << 16);
    }
}

// B' rows: [hi | hi | lo]
__global__ void __launch_bounds__(256) prep_B(const float* __restrict__ cb) {
    int idx = blockIdx.x * 256 + threadIdx.x;   // 0 .. 8192*96-1
    int row = idx / 96;
    int c   = idx % 96;
    int blk = c >> 5;                 // 0:hi 1:hi 2:lo
    int d0  = (c & 31) * 2;
    float v0 = cb[(size_t)row * 64 + d0], v1 = cb[(size_t)row * 64 + d0 + 1];
    __nv_bfloat16 h0 = __float2bfloat16(v0);
    __nv_bfloat16 h1 = __float2bfloat16(v1);
    if (blk == 2) {
        h0 = __float2bfloat16(v0 - __bfloat162float(h0));
        h1 = __float2bfloat16(v1 - __bfloat162float(h1));
    }
    ((uint32_t*)d_B)[(size_t)row * 96 + c] =
        (uint32_t)__bfloat16_as_ushort(h0) | ((uint32_t)__bfloat16_as_ushort(h1) << 16);
}

// ---------------------------------------------------------------------------
// GEMM (mma.sync bf16) + fused top-2 epilogue (8 independent trackers)
// ---------------------------------------------------------------------------
__device__ __forceinline__ void load_B_tile(uint32_t sb, int t, int buf, int tid) {
#pragma unroll
    for (int i = 0; i < 6; i++) {
        int e = tid + GT * i;         // 0..1535
        int row = e / 24, c = e % 24;
        cpa16(sb + S_B + buf * 25600 + row * 400 + c * 16,
              d_B + (size_t)(t * NT + row) * KS + c * 8);
    }
    if (tid < NT)
        cpa4(sb + S_CN + buf * 256 + tid * 4, d_cn + t * NT + tid);
}

__global__ void __launch_bounds__(GT, 2) gemm_kernel() {
    extern __shared__ char smem[];
    const uint32_t sb = smem_u32(smem);
    const int tid = threadIdx.x;
    const int wid = tid >> 5;
    const int l   = tid & 31;
    const int wm  = wid & 3;          // M-warp 0..3 (32 rows each)
    const int wn  = wid >> 2;         // N-warp 0..1 (32 cols each)
    const int m0  = blockIdx.x * MT;

    // A tile (once, grouped with B0)
#pragma unroll
    for (int i = 0; i < 12; i++) {
        int e = tid + GT * i;         // 0..3071
        int row = e / 24, c = e % 24;
        cpa16(sb + S_A + row * 400 + c * 16, d_A + (size_t)(m0 + row) * KS + c * 8);
    }
    load_B_tile(sb, 0, 0, tid);
    CP_COMMIT();
    load_B_tile(sb, 1, 1, tid);
    CP_COMMIT();
    CP_WAIT1();
    __syncthreads();                  // A + B0 ready

    // ldmatrix per-thread base addresses
    const uint32_t aA0 = sb + S_A + (wm * 32 + (l & 15)) * 400 + (l >> 4) * 16;
    const uint32_t aA1 = aA0 + 16 * 400;
    const uint32_t bRow = (uint32_t)(wn * 32 + (l & 7) + ((l >> 3) & 1) * 8);
    const uint32_t aB0 = sb + S_B + bRow * 400 + (l >> 4) * 16;
    const uint32_t aB1 = aB0 + 16 * 400;

    // column base for this thread's epilogue slice
    const int cb0 = wn * 32 + 2 * (l & 3);

    // 8 trackers: index = row-slot (mt*2+half)*2 + (j&1)
    float b1[8], b2[8];
    int   i1[8], i2[8];
#pragma unroll
    for (int s = 0; s < 8; s++) { b1[s] = 3.4e38f; b2[s] = 3.4e38f; i1[s] = 0; i2[s] = 0; }

#pragma unroll 1
    for (int t = 0; t < NTILES; t++) {
        const int buf = t & 1;
        const uint32_t boff = (uint32_t)buf * 25600;

        float acc[2][4][4];
#pragma unroll
        for (int mt = 0; mt < 2; mt++)
#pragma unroll
            for (int j = 0; j < 4; j++)
#pragma unroll
                for (int q = 0; q < 4; q++) acc[mt][j][q] = 0.f;

#pragma unroll
        for (int ks = 0; ks < 12; ks++) {
            const uint32_t koff = (uint32_t)(ks * 32);   // 16 bf16 = 32 B
            uint32_t ra0[4], ra1[4], rb01[4], rb23[4];
            ldm_x4(ra0,  aA0 + koff);
            ldm_x4(ra1,  aA1 + koff);
            ldm_x4(rb01, aB0 + boff + koff);
            ldm_x4(rb23, aB1 + boff + koff);
            mma_bf16(acc[0][0], ra0, rb01[0], rb01[2]);
            mma_bf16(acc[0][1], ra0, rb01[1], rb01[3]);
            mma_bf16(acc[0][2], ra0, rb23[0], rb23[2]);
            mma_bf16(acc[0][3], ra0, rb23[1], rb23[3]);
            mma_bf16(acc[1][0], ra1, rb01[0], rb01[2]);
            mma_bf16(acc[1][1], ra1, rb01[1], rb01[3]);
            mma_bf16(acc[1][2], ra1, rb23[0], rb23[2]);
            mma_bf16(acc[1][3], ra1, rb23[1], rb23[3]);
        }

        // epilogue: score = nc - 2*m; 8 independent top-2 chains (depth 4 each)
        const float* cnp = (const float*)(smem + S_CN + buf * 256);
        const int kb0 = t * NT + cb0;
#pragma unroll
        for (int j = 0; j < 4; j++) {
            float c0 = cnp[cb0 + j * 8];
            float c1 = cnp[cb0 + j * 8 + 1];
            int kk = kb0 + j * 8;
            const int par = j & 1;
#pragma unroll
            for (int mt = 0; mt < 2; mt++) {
                const int s0 = (mt * 2) * 2 + par;      // rows r, r+8
                const int s1 = (mt * 2 + 1) * 2 + par;
                float v0 = fmaf(-2.f, acc[mt][j][0], c0);
                float v1 = fmaf(-2.f, acc[mt][j][1], c1);
                float v2 = fmaf(-2.f, acc[mt][j][2], c0);
                float v3 = fmaf(-2.f, acc[mt][j][3], c1);
                if (v0 < b1[s0]) { b2[s0] = b1[s0]; i2[s0] = i1[s0]; b1[s0] = v0; i1[s0] = kk; }
                else if (v0 < b2[s0]) { b2[s0] = v0; i2[s0] = kk; }
                if (v1 < b1[s0]) { b2[s0] = b1[s0]; i2[s0] = i1[s0]; b1[s0] = v1; i1[s0] = kk + 1; }
                else if (v1 < b2[s0]) { b2[s0] = v1; i2[s0] = kk + 1; }
                if (v2 < b1[s1]) { b2[s1] = b1[s1]; i2[s1] = i1[s1]; b1[s1] = v2; i1[s1] = kk; }
                else if (v2 < b2[s1]) { b2[s1] = v2; i2[s1] = kk; }
                if (v3 < b1[s1]) { b2[s1] = b1[s1]; i2[s1] = i1[s1]; b1[s1] = v3; i1[s1] = kk + 1; }
                else if (v3 < b2[s1]) { b2[s1] = v3; i2[s1] = kk + 1; }
            }
        }

        __syncthreads();                       // everyone done reading buf
        if (t + 2 < NTILES) load_B_tile(sb, t + 2, buf, tid);
        CP_COMMIT();
        CP_WAIT1();                            // B(t+1) ready
        __syncthreads();
    }

    // merge tracker pairs (even/odd j) -> 4 row slots
    float m1[4], m2[4];
    int   n1[4], n2i[4];
#pragma unroll
    for (int s = 0; s < 4; s++) {
        float a1 = b1[2 * s], a2 = b2[2 * s];
        int   x1 = i1[2 * s], x2 = i2[2 * s];
        float c1v = b1[2 * s + 1], c2v = b2[2 * s + 1];
        int   y1 = i1[2 * s + 1], y2 = i2[2 * s + 1];
        if (c1v < a1) {
            float t2v = fminf(a1, c2v);
            int   t2i = (c2v < a1) ? y2 : x1;
            a2 = t2v; x2 = t2i;
            a1 = c1v; x1 = y1;
        } else if (c1v < a2) {
            a2 = c1v; x2 = y1;
        }
        m1[s] = a1; n1[s] = x1; m2[s] = a2; n2i[s] = x2;
    }

    // quad merge (lanes sharing l>>2 hold same rows)
#pragma unroll
    for (int s = 0; s < 4; s++) {
#pragma unroll
        for (int off = 1; off <= 2; off <<= 1) {
            float t1 = __shfl_xor_sync(0xFFFFFFFFu, m1[s], off);
            int   j1 = __shfl_xor_sync(0xFFFFFFFFu, n1[s], off);
            float t2 = __shfl_xor_sync(0xFFFFFFFFu, m2[s], off);
            int   j2 = __shfl_xor_sync(0xFFFFFFFFu, n2i[s], off);
            if (t1 < m1[s]) {
                float nb2 = fminf(m1[s], t2);
                int   ni2 = (t2 < m1[s]) ? j2 : n1[s];
                m1[s] = t1; n1[s] = j1; m2[s] = nb2; n2i[s] = ni2;
            } else if (t1 < m2[s]) {
                m2[s] = t1; n2i[s] = j1;
            }
        }
    }

    // cross-N-warp merge via smem (reuse B region)
    float4* red = (float4*)(smem + S_B);       // [128 rows][2 wn]
    if ((l & 3) == 0) {
#pragma unroll
        for (int s = 0; s < 4; s++) {
            int row = wm * 32 + (s >> 1) * 16 + (s & 1) * 8 + (l >> 2);
            red[row * 2 + wn] = make_float4(m1[s], __int_as_float(n1[s]),
                                            m2[s], __int_as_float(n2i[s]));
        }
    }
    __syncthreads();
    if (tid < MT) {
        float4 A4 = red[tid * 2 + 0];
        float4 B4 = red[tid * 2 + 1];
        float s1 = A4.x, s2 = A4.z;
        int   k1 = __float_as_int(A4.y), k2 = __float_as_int(A4.w);
        float t1 = B4.x, t2 = B4.z;
        int   j1 = __float_as_int(B4.y), j2 = __float_as_int(B4.w);
        if (t1 < s1) {
            float n2v = fminf(s1, t2);
            int   n2x = (t2 < s1) ? j2 : k1;
            s1 = t1; k1 = j1; s2 = n2v; k2 = n2x;
        } else if (t1 < s2) {
            s2 = t1; k2 = j1;
        }
        d_cand[m0 + tid] = make_int2(k1, k2);
    }
}

// ---------------------------------------------------------------------------
// finalize: exact rescore (reference-identical rounding) + gather, fused.
// Block = 128 threads, 64 points.
// ---------------------------------------------------------------------------
__global__ void __launch_bounds__(128) finalize(const float* __restrict__ ze,
                                                const float* __restrict__ cb,
                                                float* __restrict__ out) {
    __shared__ int bx[64];
    const int tid = threadIdx.x;
    const int n0  = blockIdx.x * 64;
    const int b   = n0 >> 12;
    const int hw0 = n0 & 4095;

    if (tid < 64) {
        const int n  = n0 + tid;
        const int hw = hw0 + tid;
        float x[DIM];
#pragma unroll
        for (int d = 0; d < DIM; d++)
            x[d] = ze[(size_t)(b * DIM + d) * 4096 + hw];
        float nx = 0.f;
#pragma unroll
        for (int d = 0; d < DIM; d++)
            nx = __fadd_rn(nx, __fmul_rn(x[d], x[d]));
        int2 cd = d_cand[n];
        int ka = min(cd.x, cd.y), kb = max(cd.x, cd.y);
        const float* ra = cb + (size_t)ka * DIM;
        const float* rb = cb + (size_t)kb * DIM;
        float ma = 0.f, mb = 0.f;
#pragma unroll
        for (int d = 0; d < DIM; d++) {
            ma = __fmaf_rn(x[d], ra[d], ma);
            mb = __fmaf_rn(x[d], rb[d], mb);
        }
        float d2a = __fadd_rn(__fadd_rn(nx, -__fmul_rn(2.0f, ma)), d_cn[ka]);
        float d2b = __fadd_rn(__fadd_rn(nx, -__fmul_rn(2.0f, mb)), d_cn[kb]);
        bx[tid] = (d2b < d2a) ? kb : ka;   // strict: tie -> lower index
    }
    __syncthreads();

    float* ob = out + (size_t)b * DIM * 4096 + hw0;
#pragma unroll
    for (int it = 0; it < 32; it++) {
        int e = tid + it * 128;
        int nl = e & 63, d = e >> 6;
        ob[(size_t)d * 4096 + nl] = cb[(size_t)bx[nl] * DIM + d];
    }
}

extern "C" void kernel_launch(void* const* d_in, const int* in_sizes, int n_in,
                              void* d_out, int out_size) {
    const float* ze = (const float*)d_in[0];   // [8,64,64,64] f32
    const float* cb = (const float*)d_in[1];   // [8192,64] f32
    float* out = (float*)d_out;

    cudaFuncSetAttribute(gemm_kernel, cudaFuncAttributeMaxDynamicSharedMemorySize,
                         SMEM_G);

    prep_cn<<<KC / 256, 256>>>(cb);
    prep_A<<<NP / 64, 128>>>(ze);
    prep_B<<<(KC * 96) / 256, 256>>>(cb);
    gemm_kernel<<<NP / MT, GT, SMEM_G>>>();
    finalize<<<NP / 64, 128>>>(ze, cb, out);
}